// round 6
// baseline (speedup 1.0000x reference)
#include <cuda_runtime.h>
#include <cuda_bf16.h>
#include <cstdint>

#define B_  4
#define T_  4096
#define D_  2048
#define MT  16384          // B_*T_
#define KA  4096           // A scratch width: [hi(2048) | lo(2048)]
#define KB  6144           // B cat width:     [w_hi | w_lo | w_hi]
#define NCHUNK 96          // 6144 / 64
#define STAGE_BYTES 32768  // A 16KB + B 16KB
#define SMEM_DYN (3 * STAGE_BYTES + 1024)

// ---------------- scratch (__device__ globals; allocation is forbidden) ----------
__device__ __nv_bfloat16 g_xk[(size_t)MT * KA];
__device__ __nv_bfloat16 g_xv[(size_t)MT * KA];
__device__ __nv_bfloat16 g_xr[(size_t)MT * KA];
__device__ __nv_bfloat16 g_rw[(size_t)MT * KA];
__device__ __nv_bfloat16 g_Wkc[(size_t)D_ * KB];
__device__ __nv_bfloat16 g_Wvc[(size_t)D_ * KB];
__device__ __nv_bfloat16 g_Wrc[(size_t)D_ * KB];
__device__ __nv_bfloat16 g_Woc[(size_t)D_ * KB];
__device__ float g_k[(size_t)MT * D_];
__device__ float g_v[(size_t)MT * D_];
__device__ float g_r[(size_t)MT * D_];
__device__ float g_wkv[(size_t)MT * D_];

// ---------------- helpers ----------------
__device__ __forceinline__ uint32_t smem_u32(const void* p) {
    uint32_t a;
    asm("{ .reg .u64 t; cvta.to.shared.u64 t, %1; cvt.u32.u64 %0, t; }" : "=r"(a) : "l"(p));
    return a;
}
#define SWZ(o) ((o) ^ (((o) >> 3) & 0x70))

__device__ __forceinline__ void cp16(uint32_t s, const void* g) {
    asm volatile("cp.async.cg.shared.global [%0], [%1], 16;" :: "r"(s), "l"(g));
}
#define CP_COMMIT() asm volatile("cp.async.commit_group;" ::: "memory")

__device__ __forceinline__ void ldsm4(uint32_t* r, uint32_t a) {
    asm volatile("ldmatrix.sync.aligned.m8n8.x4.shared.b16 {%0,%1,%2,%3}, [%4];"
                 : "=r"(r[0]), "=r"(r[1]), "=r"(r[2]), "=r"(r[3]) : "r"(a));
}
__device__ __forceinline__ void ldsm2(uint32_t* r, uint32_t a) {
    asm volatile("ldmatrix.sync.aligned.m8n8.x2.shared.b16 {%0,%1}, [%2];"
                 : "=r"(r[0]), "=r"(r[1]) : "r"(a));
}
__device__ __forceinline__ void mma16816(float* c, const uint32_t* a, const uint32_t* b) {
    asm volatile("mma.sync.aligned.m16n8k16.row.col.f32.bf16.bf16.f32 "
                 "{%0,%1,%2,%3}, {%4,%5,%6,%7}, {%8,%9}, {%0,%1,%2,%3};"
                 : "+f"(c[0]), "+f"(c[1]), "+f"(c[2]), "+f"(c[3])
                 : "r"(a[0]), "r"(a[1]), "r"(a[2]), "r"(a[3]), "r"(b[0]), "r"(b[1]));
}

__device__ __forceinline__ void split2(float v, __nv_bfloat16& h, __nv_bfloat16& l) {
    h = __float2bfloat16(v);
    l = __float2bfloat16(v - __bfloat162float(h));
}

// ================= weight prep: W fp32 [D,D] -> [hi|lo|hi] bf16 [D, 6144] =========
__global__ __launch_bounds__(256) void wprep_kernel(const float* __restrict__ Wk,
                                                    const float* __restrict__ Wv,
                                                    const float* __restrict__ Wr,
                                                    const float* __restrict__ Wo) {
    int gid = blockIdx.x * blockDim.x + threadIdx.x;   // 4 * 2^20
    int mat = gid >> 20;
    int rr  = gid & 1048575;
    int e   = rr >> 9;
    int c4  = (rr & 511) << 2;
    const float* W = (mat == 0) ? Wk : (mat == 1) ? Wv : (mat == 2) ? Wr : Wo;
    __nv_bfloat16* G = (mat == 0) ? g_Wkc : (mat == 1) ? g_Wvc : (mat == 2) ? g_Wrc : g_Woc;
    float4 w = *(const float4*)(W + (size_t)e * D_ + c4);
    __nv_bfloat16 h0, h1, h2, h3, l0, l1, l2, l3;
    split2(w.x, h0, l0); split2(w.y, h1, l1); split2(w.z, h2, l2); split2(w.w, h3, l3);
    __nv_bfloat162 hp0(h0, h1), hp1(h2, h3), lp0(l0, l1), lp1(l2, l3);
    uint2 hi = make_uint2(*(uint32_t*)&hp0, *(uint32_t*)&hp1);
    uint2 lo = make_uint2(*(uint32_t*)&lp0, *(uint32_t*)&lp1);
    size_t base = (size_t)e * KB + c4;
    *(uint2*)(G + base)        = hi;
    *(uint2*)(G + base + 2048) = lo;
    *(uint2*)(G + base + 4096) = hi;
}

// ================= token-shift mix: build xk/xv/xr hi|lo bf16 [MT, 4096] ==========
__global__ __launch_bounds__(256) void mix_kernel(const float* __restrict__ x,
                                                  const float* __restrict__ tmk,
                                                  const float* __restrict__ tmv,
                                                  const float* __restrict__ tmr) {
    int gid = blockIdx.x * blockDim.x + threadIdx.x;   // MT*512
    int row = gid >> 9;
    int c4  = (gid & 511) << 2;
    size_t xoff = (size_t)row * D_ + c4;
    float4 xc = *(const float4*)(x + xoff);
    float4 xs;
    if ((row & (T_ - 1)) == 0) xs = make_float4(0.f, 0.f, 0.f, 0.f);
    else                       xs = *(const float4*)(x + xoff - D_);
    float4 tk = *(const float4*)(tmk + c4);
    float4 tv = *(const float4*)(tmv + c4);
    float4 tr = *(const float4*)(tmr + c4);
    size_t base = (size_t)row * KA + c4;

#define DO_MIX(TM, DST)                                                               \
    {                                                                                 \
        float m0 = xc.x * TM.x + xs.x * (1.f - TM.x);                                 \
        float m1 = xc.y * TM.y + xs.y * (1.f - TM.y);                                 \
        float m2 = xc.z * TM.z + xs.z * (1.f - TM.z);                                 \
        float m3 = xc.w * TM.w + xs.w * (1.f - TM.w);                                 \
        __nv_bfloat16 h0, h1, h2, h3, l0, l1, l2, l3;                                 \
        split2(m0, h0, l0); split2(m1, h1, l1); split2(m2, h2, l2); split2(m3, h3, l3);\
        __nv_bfloat162 hp0(h0, h1), hp1(h2, h3), lp0(l0, l1), lp1(l2, l3);            \
        *(uint2*)(DST + base)        = make_uint2(*(uint32_t*)&hp0, *(uint32_t*)&hp1);\
        *(uint2*)(DST + base + 2048) = make_uint2(*(uint32_t*)&lp0, *(uint32_t*)&lp1);\
    }
    DO_MIX(tk, g_xk)
    DO_MIX(tv, g_xv)
    DO_MIX(tr, g_xr)
#undef DO_MIX
}

// ================= HMMA GEMM: C[m,n] = sum_k A[m,k]*B[n,k] ========================
// A: [MT, 4096] bf16 (hi|lo); logical chunk c (of 96, 64 cols each) maps to
// physical A chunk (c&31) + (c>=64 ? 32 : 0), with B = [wh | wl | wh]:
// covers xh*wh + xh*wl + xl*wh.   epi: 1 = sigmoid before store.
__global__ void __launch_bounds__(256) gemm128(const __nv_bfloat16* __restrict__ A,
                                               const __nv_bfloat16* __restrict__ Bw,
                                               float* __restrict__ C, int epi) {
    extern __shared__ char smem[];
    uint32_t sdata = (smem_u32(smem) + 1023) & ~1023u;
    int tid = threadIdx.x, wid = tid >> 5, lane = tid & 31;
    int bid = blockIdx.x;
    int m0 = (bid >> 4) << 7;          // 16 consecutive bids share the M-tile (A L2 reuse)
    int n0 = (bid & 15) << 7;
    int warp_m = (wid & 1) * 64;       // 2 x 4 warp grid, warp tile 64x32
    int warp_n = (wid >> 1) * 32;

    const __nv_bfloat16* Arow = A + (size_t)m0 * KA;
    const __nv_bfloat16* Brow = Bw + (size_t)n0 * KB;

#define FILL(STAGE, CHUNK)                                                              \
    {                                                                                   \
        int _c = (CHUNK);                                                               \
        int _ca = (_c & 31) + ((_c >= 64) ? 32 : 0);                                    \
        const __nv_bfloat16* _Ab = Arow + _ca * 64;                                     \
        const __nv_bfloat16* _Bb = Brow + _c * 64;                                      \
        uint32_t _sA = sdata + (STAGE) * STAGE_BYTES;                                   \
        uint32_t _sB = _sA + 16384;                                                     \
        _Pragma("unroll")                                                               \
        for (int _i = 0; _i < 4; _i++) {                                                \
            int _l = tid * 4 + _i;                                                      \
            int _row = _l >> 3, _seg = _l & 7;                                          \
            uint32_t _so = SWZ((uint32_t)(_row * 128 + _seg * 16));                     \
            cp16(_sA + _so, _Ab + (size_t)_row * KA + _seg * 8);                        \
            cp16(_sB + _so, _Bb + (size_t)_row * KB + _seg * 8);                        \
        }                                                                               \
        CP_COMMIT();                                                                    \
    }

    FILL(0, 0)
    FILL(1, 1)

    float acc[4][4][4];
#pragma unroll
    for (int i = 0; i < 4; i++)
#pragma unroll
        for (int j = 0; j < 4; j++)
#pragma unroll
            for (int q = 0; q < 4; q++) acc[i][j][q] = 0.f;

    // precomputed ldmatrix lane offsets (within-tile, before SWZ)
    int a_lrow = lane & 15;
    int a_lcol = (lane >> 4) * 16;     // byte offset: 0 or 16 (8 bf16)
    int b_l = lane & 15;
    int b_row = b_l & 7;
    int b_kb = (b_l >> 3) * 16;        // byte offset: 0 or 16

    for (int c = 0; c < NCHUNK; c++) {
        if (c == NCHUNK - 1) asm volatile("cp.async.wait_group 0;" ::: "memory");
        else                 asm volatile("cp.async.wait_group 1;" ::: "memory");
        __syncthreads();
        if (c + 2 < NCHUNK) FILL((c + 2) % 3, c + 2)

        uint32_t sA = sdata + (c % 3) * STAGE_BYTES;
        uint32_t sB = sA + 16384;
#pragma unroll
        for (int ks = 0; ks < 4; ks++) {
            int k0b = ks * 32;         // byte offset of k-step (16 bf16)
            uint32_t av[4][4], bv[4][2];
#pragma unroll
            for (int mi = 0; mi < 4; mi++) {
                uint32_t off = (uint32_t)((warp_m + mi * 16 + a_lrow) * 128 + k0b + a_lcol);
                ldsm4(av[mi], sA + SWZ(off));
            }
#pragma unroll
            for (int ni = 0; ni < 4; ni++) {
                uint32_t off = (uint32_t)((warp_n + ni * 8 + b_row) * 128 + k0b + b_kb);
                ldsm2(bv[ni], sB + SWZ(off));
            }
#pragma unroll
            for (int mi = 0; mi < 4; mi++)
#pragma unroll
                for (int ni = 0; ni < 4; ni++)
                    mma16816(acc[mi][ni], av[mi], bv[ni]);
        }
    }
#undef FILL

    // epilogue: fragment layout c0,c1 -> (row g, col 2q..2q+1); c2,c3 -> row g+8
    int g = lane >> 2, tq = lane & 3;
#pragma unroll
    for (int mi = 0; mi < 4; mi++) {
#pragma unroll
        for (int ni = 0; ni < 4; ni++) {
            int row = m0 + warp_m + mi * 16 + g;
            int col = n0 + warp_n + ni * 8 + tq * 2;
            float v0 = acc[mi][ni][0], v1 = acc[mi][ni][1];
            float v2 = acc[mi][ni][2], v3 = acc[mi][ni][3];
            if (epi == 1) {
                v0 = 1.f / (1.f + __expf(-v0));
                v1 = 1.f / (1.f + __expf(-v1));
                v2 = 1.f / (1.f + __expf(-v2));
                v3 = 1.f / (1.f + __expf(-v3));
            }
            *(float2*)(C + (size_t)row * D_ + col)       = make_float2(v0, v1);
            *(float2*)(C + (size_t)(row + 8) * D_ + col) = make_float2(v2, v3);
        }
    }
}

// ================= WKV recurrence: one thread per (b,d) channel ====================
__global__ __launch_bounds__(128) void wkv_kernel(const float* __restrict__ K,
                                                  const float* __restrict__ V,
                                                  const float* __restrict__ td,
                                                  const float* __restrict__ tf,
                                                  float* __restrict__ O) {
    int ch = blockIdx.x * blockDim.x + threadIdx.x;
    if (ch >= B_ * D_) return;
    int b = ch >> 11, d = ch & (D_ - 1);
    float negew = -__expf(td[d]);
    float u = tf[d];
    const float* kp = K + (size_t)b * T_ * D_ + d;
    const float* vp = V + (size_t)b * T_ * D_ + d;
    float* op = O + (size_t)b * T_ * D_ + d;
    float aa = 0.f, bb = 0.f, pp = -1e38f;

    const int P = 16;
    float kr[P], vr[P];
#pragma unroll
    for (int j = 0; j < P; j++) { kr[j] = kp[(size_t)j * D_]; vr[j] = vp[(size_t)j * D_]; }

    for (int tb = 0; tb < T_; tb += P) {
        float kn[P], vn[P];
        int nb2 = tb + P;
        if (nb2 < T_) {
#pragma unroll
            for (int j = 0; j < P; j++) {
                kn[j] = kp[(size_t)(nb2 + j) * D_];
                vn[j] = vp[(size_t)(nb2 + j) * D_];
            }
        } else {
#pragma unroll
            for (int j = 0; j < P; j++) { kn[j] = 0.f; vn[j] = 0.f; }
        }
#pragma unroll
        for (int j = 0; j < P; j++) {
            float kt = kr[j], vt = vr[j];
            float ku = kt + u;
            float qt = fmaxf(pp, ku);
            float e1 = __expf(pp - qt), e2 = __expf(ku - qt);
            float outv = __fdividef(e1 * aa + e2 * vt, e1 * bb + e2);
            float ppn = fmaxf(pp + negew, kt);
            float f1 = __expf(pp - ppn), f2 = __expf(kt - ppn);
            aa = f1 * aa + f2 * vt;
            bb = f1 * bb + f2;
            pp = ppn;
            op[(size_t)(tb + j) * D_] = outv;
        }
#pragma unroll
        for (int j = 0; j < P; j++) { kr[j] = kn[j]; vr[j] = vn[j]; }
    }
}

// ================= LayerNorm + r-gate + bf16 split: g_rw = split(r * LN(wkv)) =====
__global__ __launch_bounds__(256) void ln_kernel(const float* __restrict__ wkv,
                                                 const float* __restrict__ r,
                                                 const float* __restrict__ lng,
                                                 const float* __restrict__ lnb) {
    int row = blockIdx.x;
    int tid = threadIdx.x, wid = tid >> 5, lid = tid & 31;
    const float* wr = wkv + (size_t)row * D_;
    int c0 = tid * 8;
    float4 a = *(const float4*)(wr + c0);
    float4 b2 = *(const float4*)(wr + c0 + 4);
    float s = a.x + a.y + a.z + a.w + b2.x + b2.y + b2.z + b2.w;
    float q = a.x * a.x + a.y * a.y + a.z * a.z + a.w * a.w +
              b2.x * b2.x + b2.y * b2.y + b2.z * b2.z + b2.w * b2.w;
#pragma unroll
    for (int o = 16; o > 0; o >>= 1) {
        s += __shfl_xor_sync(0xFFFFFFFF, s, o);
        q += __shfl_xor_sync(0xFFFFFFFF, q, o);
    }
    __shared__ float red[2][8];
    if (lid == 0) { red[0][wid] = s; red[1][wid] = q; }
    __syncthreads();
    float ts = 0.f, tq = 0.f;
#pragma unroll
    for (int i = 0; i < 8; i++) { ts += red[0][i]; tq += red[1][i]; }
    float mu = ts * (1.f / D_);
    float var = tq * (1.f / D_) - mu * mu;
    float rstd = rsqrtf(var + 1e-5f);

    float4 g0 = *(const float4*)(lng + c0);
    float4 g1 = *(const float4*)(lng + c0 + 4);
    float4 bb0 = *(const float4*)(lnb + c0);
    float4 bb1 = *(const float4*)(lnb + c0 + 4);
    float4 r0 = *(const float4*)(r + (size_t)row * D_ + c0);
    float4 r1 = *(const float4*)(r + (size_t)row * D_ + c0 + 4);

    float vals[8] = {a.x, a.y, a.z, a.w, b2.x, b2.y, b2.z, b2.w};
    float gg[8] = {g0.x, g0.y, g0.z, g0.w, g1.x, g1.y, g1.z, g1.w};
    float bbv[8] = {bb0.x, bb0.y, bb0.z, bb0.w, bb1.x, bb1.y, bb1.z, bb1.w};
    float rv[8] = {r0.x, r0.y, r0.z, r0.w, r1.x, r1.y, r1.z, r1.w};

    __nv_bfloat16 hi[8], lo[8];
#pragma unroll
    for (int j = 0; j < 8; j++) {
        float ln = (vals[j] - mu) * rstd * gg[j] + bbv[j];
        split2(rv[j] * ln, hi[j], lo[j]);
    }
    size_t base = (size_t)row * KA + c0;
    *(uint4*)(g_rw + base)        = *(uint4*)hi;
    *(uint4*)(g_rw + base + 2048) = *(uint4*)lo;
}

// ================= launch =========================================================
extern "C" void kernel_launch(void* const* d_in, const int* in_sizes, int n_in,
                              void* d_out, int out_size) {
    const float* x   = (const float*)d_in[0];
    const float* Wk  = (const float*)d_in[1];
    const float* Wv  = (const float*)d_in[2];
    const float* Wr  = (const float*)d_in[3];
    const float* Wo  = (const float*)d_in[4];
    const float* tmk = (const float*)d_in[5];
    const float* tmv = (const float*)d_in[6];
    const float* tmr = (const float*)d_in[7];
    const float* td  = (const float*)d_in[8];
    const float* tf  = (const float*)d_in[9];
    const float* lng = (const float*)d_in[10];
    const float* lnb = (const float*)d_in[11];
    float* out = (float*)d_out;

    cudaFuncSetAttribute(gemm128, cudaFuncAttributeMaxDynamicSharedMemorySize, SMEM_DYN);

    void *pxk, *pxv, *pxr, *prw, *pwk, *pwv, *pwr, *pwo, *pk, *pv, *pr, *pwkv;
    cudaGetSymbolAddress(&pxk, g_xk);  cudaGetSymbolAddress(&pxv, g_xv);
    cudaGetSymbolAddress(&pxr, g_xr);  cudaGetSymbolAddress(&prw, g_rw);
    cudaGetSymbolAddress(&pwk, g_Wkc); cudaGetSymbolAddress(&pwv, g_Wvc);
    cudaGetSymbolAddress(&pwr, g_Wrc); cudaGetSymbolAddress(&pwo, g_Woc);
    cudaGetSymbolAddress(&pk, g_k);    cudaGetSymbolAddress(&pv, g_v);
    cudaGetSymbolAddress(&pr, g_r);    cudaGetSymbolAddress(&pwkv, g_wkv);

    wprep_kernel<<<16384, 256>>>(Wk, Wv, Wr, Wo);
    mix_kernel<<<32768, 256>>>(x, tmk, tmv, tmr);

    gemm128<<<2048, 256, SMEM_DYN>>>((const __nv_bfloat16*)pxk, (const __nv_bfloat16*)pwk,
                                     (float*)pk, 0);
    gemm128<<<2048, 256, SMEM_DYN>>>((const __nv_bfloat16*)pxv, (const __nv_bfloat16*)pwv,
                                     (float*)pv, 0);
    gemm128<<<2048, 256, SMEM_DYN>>>((const __nv_bfloat16*)pxr, (const __nv_bfloat16*)pwr,
                                     (float*)pr, 1);

    wkv_kernel<<<64, 128>>>((const float*)pk, (const float*)pv, td, tf, (float*)pwkv);
    ln_kernel<<<16384, 256>>>((const float*)pwkv, (const float*)pr, lng, lnb);

    gemm128<<<2048, 256, SMEM_DYN>>>((const __nv_bfloat16*)prw, (const __nv_bfloat16*)pwo,
                                     out, 0);
}